// round 3
// baseline (speedup 1.0000x reference)
#include <cuda_runtime.h>
#include <math.h>
#include <math_constants.h>

#define D_MODEL 768
#define N_BR    4
#define DH      64
#define H_TOT   48
#define BATCH   2
#define T_LEN   1024
#define M_ROWS  2048
#define NQ      3072

typedef unsigned long long u64;

// ---- packed fp32x2 helpers (sm_100 FFMA2) ----
__device__ __forceinline__ u64 f2fma(u64 a, u64 b, u64 c) {
    u64 d; asm("fma.rn.f32x2 %0, %1, %2, %3;" : "=l"(d) : "l"(a), "l"(b), "l"(c)); return d;
}
__device__ __forceinline__ u64 f2pack(float lo, float hi) {
    u64 d; asm("mov.b64 %0, {%1, %2};" : "=l"(d) : "f"(lo), "f"(hi)); return d;
}
__device__ __forceinline__ float2 f2unpack(u64 a) {
    float lo, hi; asm("mov.b64 {%0, %1}, %2;" : "=f"(lo), "=f"(hi) : "l"(a)); return make_float2(lo, hi);
}
__device__ __forceinline__ float f2sum(u64 a) { float2 v = f2unpack(a); return v.x + v.y; }

// ---- scratch ----
__device__ float  g_wq2  [NQ * D_MODEL];                   // folded WQ (wedge absorbed)
__device__ float  g_wot  [N_BR * D_MODEL * D_MODEL];       // WO transposed [br][n][c]
__device__ float  g_kbase[M_ROWS * D_MODEL];
__device__ float  g_qrope[BATCH * H_TOT * T_LEN * DH];
__device__ float  g_krope[BATCH * H_TOT * T_LEN * DH];
__device__ float  g_ctx  [BATCH * N_BR * T_LEN * D_MODEL];
__device__ float2 g_ropetab[T_LEN * 32];

// ================= rope cos/sin table =================
__global__ void ropetab_kernel() {
    int idx = blockIdx.x * 256 + threadIdx.x;      // 32768
    int t = idx >> 5, i = idx & 31;
    float inv = exp2f(-(float)i * 0.41524101186092034f);   // log2(10000)/32
    float fr = (float)t * inv;
    g_ropetab[idx] = make_float2(cosf(fr), sinf(fr));
}

// ================= fold wedge into WQ =================
// wq2[h*64+d][c] = (1+bias[h][d]) * WQ[h*64+d][c] + sum_e skew[e][d] * WQ[h*64+e][c]
__global__ void foldwq_kernel(const float* __restrict__ WQw,
                              const float* __restrict__ wedgeA,
                              const float* __restrict__ wbias,
                              float* __restrict__ wq2) {
    __shared__ float sk[64 * 64];
    __shared__ float Ws[64 * 68];
    const int h = blockIdx.x;
    const int c0 = blockIdx.y * 64;
    const int tid = threadIdx.x;   // 256
    for (int i = tid; i < 4096; i += 256) {
        int e = i >> 6, d = i & 63;
        sk[i] = wedgeA[e * 64 + d] - wedgeA[d * 64 + e];
    }
    for (int i = tid; i < 4096; i += 256) {
        int e = i >> 6, c = i & 63;
        Ws[e * 68 + c] = WQw[(size_t)(h * 64 + e) * D_MODEL + c0 + c];
    }
    __syncthreads();
    const int d = tid >> 2, cg = (tid & 3) * 16;
    float out[16];
    const float bd = 1.0f + wbias[h * 64 + d];
#pragma unroll
    for (int u = 0; u < 16; u++) out[u] = bd * Ws[d * 68 + cg + u];
    for (int e = 0; e < 64; ++e) {
        float s = sk[e * 64 + d];
        const float* wr = &Ws[e * 68 + cg];
#pragma unroll
        for (int u = 0; u < 16; u++) out[u] = fmaf(s, wr[u], out[u]);
    }
    float* op = &wq2[(size_t)(h * 64 + d) * D_MODEL + c0 + cg];
#pragma unroll
    for (int u = 0; u < 16; u++) op[u] = out[u];
}

// ================= transpose WO: [br][c][n] -> [br][n][c] =================
__global__ void transwo_kernel(const float* __restrict__ WOw, float* __restrict__ WOt) {
    __shared__ float tile[32][33];
    const int br = blockIdx.z;
    const int cb = blockIdx.x * 32, nb = blockIdx.y * 32;
    const int tx = threadIdx.x & 31, ty = threadIdx.x >> 5;    // 32x8
    for (int r = ty; r < 32; r += 8)
        tile[r][tx] = WOw[((size_t)br * D_MODEL + cb + r) * D_MODEL + nb + tx];
    __syncthreads();
    for (int r = ty; r < 32; r += 8)
        WOt[((size_t)br * D_MODEL + nb + r) * D_MODEL + cb + tx] = tile[tx][r];
}

// ================= GEMM K-proj: kbase = X @ WK^T + b  (2048x768, K=768) ===========
__global__ __launch_bounds__(256) void gemm_k_kernel(const float* __restrict__ A,
                                                     const float* __restrict__ W,
                                                     const float* __restrict__ bias,
                                                     float* __restrict__ C) {
    __shared__ float As[128 * 20];
    __shared__ float Bs[64 * 20];
    const int tid = threadIdx.x;
    const int tx = tid & 15, ty = tid >> 4;
    const int m0 = blockIdx.y * 128, n0 = blockIdx.x * 64;
    const int lr = tid >> 2, lc = (tid & 3) * 4;

    u64 acc[8][4];
#pragma unroll
    for (int i = 0; i < 8; i++)
#pragma unroll
        for (int j = 0; j < 4; j++) acc[i][j] = 0ull;

    float4 pa0 = *(const float4*)&A[(size_t)(m0 + lr) * 768 + lc];
    float4 pa1 = *(const float4*)&A[(size_t)(m0 + lr + 64) * 768 + lc];
    float4 pb  = *(const float4*)&W[(size_t)(n0 + lr) * 768 + lc];

    for (int k0 = 0; k0 < 768; k0 += 16) {
        *(float4*)&As[lr * 20 + lc] = pa0;
        *(float4*)&As[(lr + 64) * 20 + lc] = pa1;
        *(float4*)&Bs[lr * 20 + lc] = pb;
        __syncthreads();
        if (k0 + 16 < 768) {
            pa0 = *(const float4*)&A[(size_t)(m0 + lr) * 768 + k0 + 16 + lc];
            pa1 = *(const float4*)&A[(size_t)(m0 + lr + 64) * 768 + k0 + 16 + lc];
            pb  = *(const float4*)&W[(size_t)(n0 + lr) * 768 + k0 + 16 + lc];
        }
#pragma unroll
        for (int kk = 0; kk < 16; kk += 4) {
            u64 av[8][2], bv[4][2];
#pragma unroll
            for (int i = 0; i < 8; i++) {
                const u64* p = (const u64*)&As[(ty * 8 + i) * 20 + kk];
                av[i][0] = p[0]; av[i][1] = p[1];
            }
#pragma unroll
            for (int j = 0; j < 4; j++) {
                const u64* p = (const u64*)&Bs[(tx * 4 + j) * 20 + kk];
                bv[j][0] = p[0]; bv[j][1] = p[1];
            }
#pragma unroll
            for (int i = 0; i < 8; i++)
#pragma unroll
                for (int j = 0; j < 4; j++) {
                    acc[i][j] = f2fma(av[i][0], bv[j][0], acc[i][j]);
                    acc[i][j] = f2fma(av[i][1], bv[j][1], acc[i][j]);
                }
        }
        __syncthreads();
    }
#pragma unroll
    for (int i = 0; i < 8; i++) {
        const int m = m0 + ty * 8 + i;
        float4 v;
        v.x = f2sum(acc[i][0]) + bias[n0 + tx * 4 + 0];
        v.y = f2sum(acc[i][1]) + bias[n0 + tx * 4 + 1];
        v.z = f2sum(acc[i][2]) + bias[n0 + tx * 4 + 2];
        v.w = f2sum(acc[i][3]) + bias[n0 + tx * 4 + 3];
        *(float4*)&C[(size_t)m * 768 + n0 + tx * 4] = v;
    }
}

// ================= GEMM Q-proj (folded wedge) + rope epilogue ====================
// C logical [m][n], n = h*64 + d' (pre-rope pairs); writes qrope[b][h][t][d]
__global__ __launch_bounds__(256) void gemm_q_kernel(const float* __restrict__ A,
                                                     const float* __restrict__ W,
                                                     float* __restrict__ qrope) {
    __shared__ float As[128 * 20];
    __shared__ float Bs[64 * 20];
    const int tid = threadIdx.x;
    const int tx = tid & 15, ty = tid >> 4;
    const int m0 = blockIdx.y * 128, n0 = blockIdx.x * 64;
    const int lr = tid >> 2, lc = (tid & 3) * 4;

    u64 acc[8][4];
#pragma unroll
    for (int i = 0; i < 8; i++)
#pragma unroll
        for (int j = 0; j < 4; j++) acc[i][j] = 0ull;

    float4 pa0 = *(const float4*)&A[(size_t)(m0 + lr) * 768 + lc];
    float4 pa1 = *(const float4*)&A[(size_t)(m0 + lr + 64) * 768 + lc];
    float4 pb  = *(const float4*)&W[(size_t)(n0 + lr) * 768 + lc];

    for (int k0 = 0; k0 < 768; k0 += 16) {
        *(float4*)&As[lr * 20 + lc] = pa0;
        *(float4*)&As[(lr + 64) * 20 + lc] = pa1;
        *(float4*)&Bs[lr * 20 + lc] = pb;
        __syncthreads();
        if (k0 + 16 < 768) {
            pa0 = *(const float4*)&A[(size_t)(m0 + lr) * 768 + k0 + 16 + lc];
            pa1 = *(const float4*)&A[(size_t)(m0 + lr + 64) * 768 + k0 + 16 + lc];
            pb  = *(const float4*)&W[(size_t)(n0 + lr) * 768 + k0 + 16 + lc];
        }
#pragma unroll
        for (int kk = 0; kk < 16; kk += 4) {
            u64 av[8][2], bv[4][2];
#pragma unroll
            for (int i = 0; i < 8; i++) {
                const u64* p = (const u64*)&As[(ty * 8 + i) * 20 + kk];
                av[i][0] = p[0]; av[i][1] = p[1];
            }
#pragma unroll
            for (int j = 0; j < 4; j++) {
                const u64* p = (const u64*)&Bs[(tx * 4 + j) * 20 + kk];
                bv[j][0] = p[0]; bv[j][1] = p[1];
            }
#pragma unroll
            for (int i = 0; i < 8; i++)
#pragma unroll
                for (int j = 0; j < 4; j++) {
                    acc[i][j] = f2fma(av[i][0], bv[j][0], acc[i][j]);
                    acc[i][j] = f2fma(av[i][1], bv[j][1], acc[i][j]);
                }
        }
        __syncthreads();
    }
    // rope epilogue: this n-tile is exactly head h = blockIdx.x; d0 = tx*4
    const int h = blockIdx.x;
    const int i0 = tx * 2;   // rope pair indices i0, i0+1
#pragma unroll
    for (int i = 0; i < 8; i++) {
        const int m = m0 + ty * 8 + i;
        const int t = m & 1023, bb = m >> 10;
        float2 rc0 = g_ropetab[t * 32 + i0];
        float2 rc1 = g_ropetab[t * 32 + i0 + 1];
        float x0 = f2sum(acc[i][0]);
        float x1 = f2sum(acc[i][1]);
        float x2 = f2sum(acc[i][2]);
        float x3 = f2sum(acc[i][3]);
        float* qp = &qrope[(((size_t)(bb * H_TOT + h)) * T_LEN + t) * DH];
        *(float2*)&qp[i0]      = make_float2(x0 * rc0.x - x1 * rc0.y, x2 * rc1.x - x3 * rc1.y);
        *(float2*)&qp[i0 + 32] = make_float2(x0 * rc0.y + x1 * rc0.x, x2 * rc1.y + x3 * rc1.x);
    }
}

// ================= K wedge + rope: kbase -> krope[b][h][t][d] ====================
// dynamic smem: Ms 64*64 floats + kbs 128*65 floats = 49664 bytes
__global__ __launch_bounds__(128) void kwr_kernel(const float* __restrict__ kbase,
                                                  const float* __restrict__ wedgeA,
                                                  const float* __restrict__ wbias,
                                                  float* __restrict__ krope) {
    extern __shared__ float kwr_sm[];
    float* Ms  = kwr_sm;            // 4096 floats
    float* kbs = kwr_sm + 4096;     // 128*65 floats
    const int h = blockIdx.y, hj = h % 12;
    const int m0 = blockIdx.x * 128;
    const int tid = threadIdx.x;

    for (int i = tid; i < 4096; i += 128) {
        int e = i >> 6, d = i & 63;
        float v = wedgeA[e * 64 + d] - wedgeA[d * 64 + e];
        if (e == d) v += 1.0f + wbias[h * 64 + d];
        Ms[i] = v;
    }
    for (int i = tid; i < 2048; i += 128) {
        int r = i >> 4, c4 = (i & 15) * 4;
        float4 v = *(const float4*)&kbase[(size_t)(m0 + r) * 768 + hj * 64 + c4];
        float* dst = &kbs[r * 65 + c4];
        dst[0] = v.x; dst[1] = v.y; dst[2] = v.z; dst[3] = v.w;
    }
    __syncthreads();

    const int m = m0 + tid, b = m >> 10, t = m & 1023;
    u64 acc2[32];
#pragma unroll
    for (int i = 0; i < 32; i++) acc2[i] = 0ull;
    const float* kr = &kbs[tid * 65];
    for (int e = 0; e < 64; ++e) {
        float kv = kr[e];
        u64 kv2 = f2pack(kv, kv);
        const u64* ms = (const u64*)&Ms[e * 64];
#pragma unroll
        for (int i = 0; i < 32; i++) acc2[i] = f2fma(kv2, ms[i], acc2[i]);
    }
    float* kp = &krope[(((size_t)(b * H_TOT + h)) * T_LEN + t) * DH];
    const float2* rt = &g_ropetab[t * 32];
#pragma unroll
    for (int i = 0; i < 32; i++) {
        float2 w = f2unpack(acc2[i]);
        float2 rc = rt[i];
        kp[i]      = w.x * rc.x - w.y * rc.y;
        kp[i + 32] = w.x * rc.y + w.y * rc.x;
    }
}

// ================= fused attention: scores + online softmax + top4 + MLP =========
__global__ __launch_bounds__(256) void attn_kernel(const float* __restrict__ qrope,
                                                   const float* __restrict__ krope,
                                                   const float* __restrict__ sink,
                                                   const float* __restrict__ vnull,
                                                   const float* __restrict__ V1w,
                                                   const float* __restrict__ V1b,
                                                   const float* __restrict__ V2w,
                                                   const float* __restrict__ V2b,
                                                   float* __restrict__ ctx) {
    extern __shared__ float sm[];       // >= 33280 floats
    __shared__ float sV1b[256];

    const int bh = blockIdx.y;               // 0..95
    const int b = bh / H_TOT, h = bh % H_TOT;
    const int xt = (gridDim.x - 1) - blockIdx.x;   // heavy tiles first
    const int t = xt * 256 + threadIdx.x;

    // q row packed as f32x2
    u64 q2[32];
    {
        const ulonglong2* qp = (const ulonglong2*)&qrope[((size_t)bh * T_LEN + t) * DH];
#pragma unroll
        for (int i = 0; i < 16; i++) { ulonglong2 v = qp[i]; q2[2 * i] = v.x; q2[2 * i + 1] = v.y; }
    }

    float mrun = -CUDART_INF_F, lrun = 0.f;
    float ts0 = -CUDART_INF_F, ts1 = -CUDART_INF_F, ts2 = -CUDART_INF_F, ts3 = -CUDART_INF_F;
    int ti0 = 0, ti1 = 0, ti2 = 0, ti3 = 0;

    float* ks = sm;
    const int sEnd = xt * 256 + 255;

    for (int s0 = 0; s0 <= sEnd; s0 += 128) {
        __syncthreads();
        {
            const float4* kg = (const float4*)&krope[((size_t)bh * T_LEN + s0) * DH];
            float4* d4 = (float4*)ks;
            for (int i = threadIdx.x; i < 2048; i += 256) d4[i] = kg[i];
        }
        __syncthreads();

        const int sMax = min(t, s0 + 127);
        for (int s = s0; s <= sMax; ++s) {
            const ulonglong2* kr = (const ulonglong2*)(ks + (s - s0) * DH);
            u64 a0 = 0ull, a1 = 0ull, a2 = 0ull, a3 = 0ull;
#pragma unroll
            for (int i = 0; i < 16; i += 2) {
                ulonglong2 kva = kr[i];
                ulonglong2 kvb = kr[i + 1];
                a0 = f2fma(q2[2 * i],     kva.x, a0);
                a1 = f2fma(q2[2 * i + 1], kva.y, a1);
                a2 = f2fma(q2[2 * i + 2], kvb.x, a2);
                a3 = f2fma(q2[2 * i + 3], kvb.y, a3);
            }
            float sc = ((f2sum(a0) + f2sum(a1)) + (f2sum(a2) + f2sum(a3))) * 0.125f;

            if (sc <= mrun) {
                lrun += __expf(sc - mrun);
            } else {
                lrun = fmaf(lrun, __expf(mrun - sc), 1.0f);
                mrun = sc;
            }
            if (sc > ts3) {
                if (sc > ts2) {
                    ts3 = ts2; ti3 = ti2;
                    if (sc > ts1) {
                        ts2 = ts1; ti2 = ti1;
                        if (sc > ts0) {
                            ts1 = ts0; ti1 = ti0;
                            ts0 = sc; ti0 = s;
                        } else { ts1 = sc; ti1 = s; }
                    } else { ts2 = sc; ti2 = s; }
                } else { ts3 = sc; ti3 = s; }
            }
        }
    }

    // final normalization with sink
    const float sk = sink[h];
    const float mf = fmaxf(mrun, sk);
    const float Z = lrun * __expf(mrun - mf) + __expf(sk - mf);
    const float invZ = 1.0f / Z;
    const float psink = __expf(sk - mf) * invZ;
    float p0 = __expf(ts0 - mf) * invZ;
    float p1 = __expf(ts1 - mf) * invZ;
    float p2 = __expf(ts2 - mf) * invZ;
    float p3 = __expf(ts3 - mf) * invZ;
    const float winv = 1.0f / (p0 + p1 + p2 + p3 + 1e-9f);
    p0 *= winv; p1 *= winv; p2 *= winv; p3 *= winv;

    // marker gather (f32x2)
    u64 mk[32];
    {
        u64 w0 = f2pack(p0, p0), w1 = f2pack(p1, p1), w2 = f2pack(p2, p2), w3 = f2pack(p3, p3);
        const ulonglong2* kp0 = (const ulonglong2*)&krope[((size_t)bh * T_LEN + ti0) * DH];
        const ulonglong2* kp1 = (const ulonglong2*)&krope[((size_t)bh * T_LEN + ti1) * DH];
        const ulonglong2* kp2 = (const ulonglong2*)&krope[((size_t)bh * T_LEN + ti2) * DH];
        const ulonglong2* kp3 = (const ulonglong2*)&krope[((size_t)bh * T_LEN + ti3) * DH];
#pragma unroll
        for (int i = 0; i < 16; i++) {
            ulonglong2 va = kp0[i], vb = kp1[i], vc = kp2[i], vd = kp3[i];
            mk[2 * i]     = f2fma(w0, va.x, f2fma(w1, vb.x, f2fma(w2, vc.x, f2fma(w3, vd.x, 0ull))));
            mk[2 * i + 1] = f2fma(w0, va.y, f2fma(w1, vb.y, f2fma(w2, vc.y, f2fma(w3, vd.y, 0ull))));
        }
    }

    // stage V1 (row-major) and V2^T (pad 66) into smem
    __syncthreads();
    float* V1s = sm;                 // 16384 floats
    float* V2t = sm + 16384;         // 256*66 floats
    for (int i = threadIdx.x; i < 4096; i += 256) ((float4*)V1s)[i] = ((const float4*)V1w)[i];
    for (int i = threadIdx.x; i < 16384; i += 256) {
        int dd = i >> 8, j = i & 255;
        V2t[j * 66 + dd] = V2w[i];
    }
    if (threadIdx.x < 256) sV1b[threadIdx.x] = V1b[threadIdx.x];
    __syncthreads();

    u64 out2[32];
    {
        const u64* vb2 = (const u64*)V2b;
#pragma unroll
        for (int i = 0; i < 32; i++) out2[i] = vb2[i];
    }

    for (int j = 0; j < 256; ++j) {
        const ulonglong2* v1 = (const ulonglong2*)(V1s + j * 64);
        u64 z0 = 0ull, z1 = 0ull, z2 = 0ull, z3 = 0ull;
#pragma unroll
        for (int i = 0; i < 16; i += 2) {
            ulonglong2 va = v1[i];
            ulonglong2 vb = v1[i + 1];
            z0 = f2fma(mk[2 * i],     va.x, z0);
            z1 = f2fma(mk[2 * i + 1], va.y, z1);
            z2 = f2fma(mk[2 * i + 2], vb.x, z2);
            z3 = f2fma(mk[2 * i + 3], vb.y, z3);
        }
        float z = ((f2sum(z0) + f2sum(z1)) + (f2sum(z2) + f2sum(z3))) + sV1b[j];
        float g = 0.5f * z * (1.0f + erff(z * 0.70710678118f));
        u64 g2 = f2pack(g, g);
        const u64* v2 = (const u64*)(V2t + j * 66);
#pragma unroll
        for (int i = 0; i < 32; i++) out2[i] = f2fma(g2, v2[i], out2[i]);
    }

    // write context + sink contribution
    const int br = h / 12, hj = h % 12;
    float* outp = &g_ctx[(((size_t)(b * N_BR + br)) * T_LEN + t) * D_MODEL + hj * 64];
    const float* vn = vnull + h * 64;
#pragma unroll
    for (int i = 0; i < 32; i++) {
        float2 v = f2unpack(out2[i]);
        v.x = fmaf(psink, vn[2 * i], v.x);
        v.y = fmaf(psink, vn[2 * i + 1], v.y);
        ((float2*)outp)[i] = v;
    }
    (void)ctx;
}

// ================= output GEMM: Y = 0.25*sum_br ctx_br @ WOt_br^T + meanb ========
__global__ __launch_bounds__(256) void gemm_out_kernel(const float* __restrict__ ctxg,
                                                       const float* __restrict__ WOt,
                                                       const float* __restrict__ WOb,
                                                       float* __restrict__ Y) {
    __shared__ float As[128 * 20];
    __shared__ float Bs[64 * 20];
    const int tid = threadIdx.x;
    const int tx = tid & 15, ty = tid >> 4;
    const int m0 = blockIdx.y * 128, n0 = blockIdx.x * 64;
    const int lr = tid >> 2, lc = (tid & 3) * 4;

    u64 acc[8][4];
#pragma unroll
    for (int i = 0; i < 8; i++)
#pragma unroll
        for (int j = 0; j < 4; j++) acc[i][j] = 0ull;

    const int ma = m0 + lr, mb2 = m0 + lr + 64;
    const int ba = ma >> 10, ta = ma & 1023;
    const int bb = mb2 >> 10, tb = mb2 & 1023;

    float4 pa0, pa1, pb;
    {
        pa0 = *(const float4*)&ctxg[(((size_t)(ba * N_BR)) * T_LEN + ta) * 768 + lc];
        pa1 = *(const float4*)&ctxg[(((size_t)(bb * N_BR)) * T_LEN + tb) * 768 + lc];
        pb  = *(const float4*)&WOt[(size_t)(n0 + lr) * 768 + lc];
    }

    for (int k0 = 0; k0 < 3072; k0 += 16) {
        *(float4*)&As[lr * 20 + lc] = pa0;
        *(float4*)&As[(lr + 64) * 20 + lc] = pa1;
        *(float4*)&Bs[lr * 20 + lc] = pb;
        __syncthreads();
        if (k0 + 16 < 3072) {
            const int kn = k0 + 16;
            const int br = kn / 768, c = kn % 768;
            pa0 = *(const float4*)&ctxg[(((size_t)(ba * N_BR + br)) * T_LEN + ta) * 768 + c + lc];
            pa1 = *(const float4*)&ctxg[(((size_t)(bb * N_BR + br)) * T_LEN + tb) * 768 + c + lc];
            pb  = *(const float4*)&WOt[((size_t)br * 768 + n0 + lr) * 768 + c + lc];
        }
#pragma unroll
        for (int kk = 0; kk < 16; kk += 4) {
            u64 av[8][2], bv[4][2];
#pragma unroll
            for (int i = 0; i < 8; i++) {
                const u64* p = (const u64*)&As[(ty * 8 + i) * 20 + kk];
                av[i][0] = p[0]; av[i][1] = p[1];
            }
#pragma unroll
            for (int j = 0; j < 4; j++) {
                const u64* p = (const u64*)&Bs[(tx * 4 + j) * 20 + kk];
                bv[j][0] = p[0]; bv[j][1] = p[1];
            }
#pragma unroll
            for (int i = 0; i < 8; i++)
#pragma unroll
                for (int j = 0; j < 4; j++) {
                    acc[i][j] = f2fma(av[i][0], bv[j][0], acc[i][j]);
                    acc[i][j] = f2fma(av[i][1], bv[j][1], acc[i][j]);
                }
        }
        __syncthreads();
    }
#pragma unroll
    for (int i = 0; i < 8; i++) {
        const int m = m0 + ty * 8 + i;
        float4 v;
#pragma unroll
        for (int j = 0; j < 4; j++) {
            const int n = n0 + tx * 4 + j;
            float mbias = 0.25f * (WOb[n] + WOb[768 + n] + WOb[1536 + n] + WOb[2304 + n]);
            float val = 0.25f * f2sum(acc[i][j]) + mbias;
            ((float*)&v)[j] = val;
        }
        *(float4*)&Y[(size_t)m * 768 + n0 + tx * 4] = v;
    }
}

// ================= launcher =================
extern "C" void kernel_launch(void* const* d_in, const int* in_sizes, int n_in,
                              void* d_out, int out_size) {
    const float* A      = (const float*)d_in[0];
    const float* X      = (const float*)d_in[1];
    const float* WKw    = (const float*)d_in[2];
    const float* WKb    = (const float*)d_in[3];
    const float* WQw    = (const float*)d_in[4];
    const float* wedgeA = (const float*)d_in[5];
    const float* wbias  = (const float*)d_in[6];
    const float* sink   = (const float*)d_in[7];
    const float* vnull  = (const float*)d_in[8];
    const float* V1w    = (const float*)d_in[9];
    const float* V1b    = (const float*)d_in[10];
    const float* V2w    = (const float*)d_in[11];
    const float* V2b    = (const float*)d_in[12];
    const float* WOw    = (const float*)d_in[13];
    const float* WOb    = (const float*)d_in[14];
    float* Y = (float*)d_out;

    float *wq2, *wot, *kbase, *qrope, *krope, *ctx;
    cudaGetSymbolAddress((void**)&wq2,   g_wq2);
    cudaGetSymbolAddress((void**)&wot,   g_wot);
    cudaGetSymbolAddress((void**)&kbase, g_kbase);
    cudaGetSymbolAddress((void**)&qrope, g_qrope);
    cudaGetSymbolAddress((void**)&krope, g_krope);
    cudaGetSymbolAddress((void**)&ctx,   g_ctx);

    cudaFuncSetAttribute(attn_kernel, cudaFuncAttributeMaxDynamicSharedMemorySize, 133120);
    cudaFuncSetAttribute(kwr_kernel,  cudaFuncAttributeMaxDynamicSharedMemorySize, 50176);

    ropetab_kernel<<<128, 256>>>();
    foldwq_kernel<<<dim3(48, 12), 256>>>(WQw, wedgeA, wbias, wq2);
    transwo_kernel<<<dim3(24, 24, 4), 256>>>(WOw, wot);
    gemm_k_kernel<<<dim3(12, 16), 256>>>(X, WKw, WKb, kbase);
    gemm_q_kernel<<<dim3(48, 16), 256>>>(A, wq2, qrope);
    kwr_kernel<<<dim3(16, 48), 128, 50176>>>(kbase, wedgeA, wbias, krope);
    attn_kernel<<<dim3(4, 96), 256, 133120>>>(qrope, krope, sink, vnull,
                                              V1w, V1b, V2w, V2b, ctx);
    gemm_out_kernel<<<dim3(12, 16), 256>>>(ctx, wot, WOb, Y);
}

// round 4
// speedup vs baseline: 1.4856x; 1.4856x over previous
#include <cuda_runtime.h>
#include <math.h>
#include <math_constants.h>

#define D_MODEL 768
#define N_BR    4
#define DH      64
#define H_TOT   48
#define BATCH   2
#define T_LEN   1024
#define M_ROWS  2048
#define NQ      3072

typedef unsigned long long u64;
typedef unsigned int u32;

// ---- packed fp32x2 helpers (used by attention kernel) ----
__device__ __forceinline__ u64 f2fma(u64 a, u64 b, u64 c) {
    u64 d; asm("fma.rn.f32x2 %0, %1, %2, %3;" : "=l"(d) : "l"(a), "l"(b), "l"(c)); return d;
}
__device__ __forceinline__ u64 f2pack(float lo, float hi) {
    u64 d; asm("mov.b64 %0, {%1, %2};" : "=l"(d) : "f"(lo), "f"(hi)); return d;
}
__device__ __forceinline__ float2 f2unpack(u64 a) {
    float lo, hi; asm("mov.b64 {%0, %1}, %2;" : "=f"(lo), "=f"(hi) : "l"(a)); return make_float2(lo, hi);
}
__device__ __forceinline__ float f2sum(u64 a) { float2 v = f2unpack(a); return v.x + v.y; }

// ---- tf32 split: x -> (hi, lo) both tf32-rounded, hi+lo ~ x to ~21 bits ----
__device__ __forceinline__ float2 tf32split(float x) {
    u32 hb; asm("cvt.rna.tf32.f32 %0, %1;" : "=r"(hb) : "f"(x));
    float hf = __uint_as_float(hb);
    float lo = x - hf;
    u32 lb; asm("cvt.rna.tf32.f32 %0, %1;" : "=r"(lb) : "f"(lo));
    return make_float2(hf, __uint_as_float(lb));
}

#define MMA_TF32(ACC, A0, A1, A2, A3, B0, B1)                                        \
    asm volatile("mma.sync.aligned.m16n8k8.row.col.f32.tf32.tf32.f32 "               \
                 "{%0,%1,%2,%3}, {%4,%5,%6,%7}, {%8,%9}, {%0,%1,%2,%3};"             \
                 : "+f"(ACC[0]), "+f"(ACC[1]), "+f"(ACC[2]), "+f"(ACC[3])            \
                 : "r"(A0), "r"(A1), "r"(A2), "r"(A3), "r"(B0), "r"(B1))

// ---- scratch ----
__device__ float  g_wq2  [NQ * D_MODEL];                   // folded WQ (wedge absorbed)
__device__ float  g_wot  [D_MODEL * NQ];                   // WO as [n][br*768+c]
__device__ float  g_kbase[M_ROWS * D_MODEL];
__device__ float  g_qrope[BATCH * H_TOT * T_LEN * DH];
__device__ float  g_krope[BATCH * H_TOT * T_LEN * DH];
__device__ float  g_ctx  [M_ROWS * NQ];                    // [b*1024+t][br*768+c]
__device__ float2 g_ropetab[T_LEN * 32];

// ================= rope cos/sin table =================
__global__ void ropetab_kernel() {
    int idx = blockIdx.x * 256 + threadIdx.x;      // 32768
    int t = idx >> 5, i = idx & 31;
    float inv = exp2f(-(float)i * 0.41524101186092034f);   // 10000^(-i/32)
    float fr = (float)t * inv;
    g_ropetab[idx] = make_float2(cosf(fr), sinf(fr));
}

// ================= fold wedge into WQ =================
__global__ void foldwq_kernel(const float* __restrict__ WQw,
                              const float* __restrict__ wedgeA,
                              const float* __restrict__ wbias,
                              float* __restrict__ wq2) {
    __shared__ float sk[64 * 64];
    __shared__ float Ws[64 * 68];
    const int h = blockIdx.x;
    const int c0 = blockIdx.y * 64;
    const int tid = threadIdx.x;   // 256
    for (int i = tid; i < 4096; i += 256) {
        int e = i >> 6, d = i & 63;
        sk[i] = wedgeA[e * 64 + d] - wedgeA[d * 64 + e];
    }
    for (int i = tid; i < 4096; i += 256) {
        int e = i >> 6, c = i & 63;
        Ws[e * 68 + c] = WQw[(size_t)(h * 64 + e) * D_MODEL + c0 + c];
    }
    __syncthreads();
    const int d = tid >> 2, cg = (tid & 3) * 16;
    float out[16];
    const float bd = 1.0f + wbias[h * 64 + d];
#pragma unroll
    for (int u = 0; u < 16; u++) out[u] = bd * Ws[d * 68 + cg + u];
    for (int e = 0; e < 64; ++e) {
        float s = sk[e * 64 + d];
        const float* wr = &Ws[e * 68 + cg];
#pragma unroll
        for (int u = 0; u < 16; u++) out[u] = fmaf(s, wr[u], out[u]);
    }
    float* op = &wq2[(size_t)(h * 64 + d) * D_MODEL + c0 + cg];
#pragma unroll
    for (int u = 0; u < 16; u++) op[u] = out[u];
}

// ================= WO relayout: [br][c][n] -> [n][br*768+c] =================
__global__ void transwo_kernel(const float* __restrict__ WOw, float* __restrict__ WOt) {
    __shared__ float tile[32][33];
    const int br = blockIdx.z;
    const int cb = blockIdx.x * 32, nb = blockIdx.y * 32;
    const int tx = threadIdx.x & 31, ty = threadIdx.x >> 5;    // 32x8
    for (int r = ty; r < 32; r += 8)
        tile[r][tx] = WOw[((size_t)br * D_MODEL + cb + r) * D_MODEL + nb + tx];
    __syncthreads();
    for (int r = ty; r < 32; r += 8)
        WOt[(size_t)(nb + r) * NQ + br * D_MODEL + cb + tx] = tile[tx][r];
}

// ================= unified tf32 (3x) NT GEMM =================
// C[m][n] = sum_k A[m*K+k] * B[n*K+k]
// CTA tile 128(M) x 64(N), 8 warps (4M x 2N), warp tile 32x32, K-step 16.
// MODE 0: out[m*768+n] = acc + aux[n]                (K projection)
// MODE 1: rope epilogue -> qrope[b][h][t][d], h = blockIdx.x
// MODE 2: out[m*768+n] = 0.25*acc + 0.25*sum_br aux[br*768+n]   (output proj)
template <int MODE>
__global__ __launch_bounds__(256) void gemm_tf32_kernel(const float* __restrict__ A,
                                                        const float* __restrict__ B,
                                                        int K,
                                                        const float* __restrict__ aux,
                                                        float* __restrict__ out) {
    __shared__ float2 As2[16 * 132];
    __shared__ float2 Bs2[16 * 68];

    const int tid = threadIdx.x;
    const int m0 = blockIdx.y * 128, n0 = blockIdx.x * 64;
    const int warpId = tid >> 5, lane = tid & 31;
    const int warpM = warpId & 3, warpN = warpId >> 2;
    const int g = lane >> 2, tg = lane & 3;

    // staging assignment
    const int sa_m = tid >> 1, sa_k = (tid & 1) * 8;     // A: row, k-base (8 wide via 2 float4)
    const int sb_n = tid & 63, sb_k = (tid >> 6) * 4;    // B: row, k-base (4 wide)

    float acc[2][4][4];
#pragma unroll
    for (int mf = 0; mf < 2; mf++)
#pragma unroll
        for (int nf = 0; nf < 4; nf++)
#pragma unroll
            for (int r = 0; r < 4; r++) acc[mf][nf][r] = 0.f;

    const float* Arow = A + (size_t)(m0 + sa_m) * K + sa_k;
    const float* Brow = B + (size_t)(n0 + sb_n) * K + sb_k;

    float4 pa0 = *(const float4*)(Arow);
    float4 pa1 = *(const float4*)(Arow + 4);
    float4 pb  = *(const float4*)(Brow);

    for (int k0 = 0; k0 < K; k0 += 16) {
        __syncthreads();
        {
            float av[8] = {pa0.x, pa0.y, pa0.z, pa0.w, pa1.x, pa1.y, pa1.z, pa1.w};
#pragma unroll
            for (int j = 0; j < 8; j++) As2[(sa_k + j) * 132 + sa_m] = tf32split(av[j]);
            float bv[4] = {pb.x, pb.y, pb.z, pb.w};
#pragma unroll
            for (int j = 0; j < 4; j++) Bs2[(sb_k + j) * 68 + sb_n] = tf32split(bv[j]);
        }
        __syncthreads();
        if (k0 + 16 < K) {
            pa0 = *(const float4*)(Arow + k0 + 16);
            pa1 = *(const float4*)(Arow + k0 + 20);
            pb  = *(const float4*)(Brow + k0 + 16);
        }
#pragma unroll
        for (int ks = 0; ks < 16; ks += 8) {
            float2 fa[2][4];
#pragma unroll
            for (int mf = 0; mf < 2; mf++) {
                const int ra = warpM * 32 + mf * 16 + g;
                const float2* c0p = &As2[(ks + tg) * 132];
                const float2* c4p = &As2[(ks + tg + 4) * 132];
                fa[mf][0] = c0p[ra];
                fa[mf][1] = c0p[ra + 8];
                fa[mf][2] = c4p[ra];
                fa[mf][3] = c4p[ra + 8];
            }
            float2 fb[4][2];
#pragma unroll
            for (int nf = 0; nf < 4; nf++) {
                const int cb = warpN * 32 + nf * 8 + g;
                fb[nf][0] = Bs2[(ks + tg) * 68 + cb];
                fb[nf][1] = Bs2[(ks + tg + 4) * 68 + cb];
            }
#pragma unroll
            for (int mf = 0; mf < 2; mf++) {
                const u32 ah0 = __float_as_uint(fa[mf][0].x), al0 = __float_as_uint(fa[mf][0].y);
                const u32 ah1 = __float_as_uint(fa[mf][1].x), al1 = __float_as_uint(fa[mf][1].y);
                const u32 ah2 = __float_as_uint(fa[mf][2].x), al2 = __float_as_uint(fa[mf][2].y);
                const u32 ah3 = __float_as_uint(fa[mf][3].x), al3 = __float_as_uint(fa[mf][3].y);
#pragma unroll
                for (int nf = 0; nf < 4; nf++) {
                    const u32 bh0 = __float_as_uint(fb[nf][0].x), bl0 = __float_as_uint(fb[nf][0].y);
                    const u32 bh1 = __float_as_uint(fb[nf][1].x), bl1 = __float_as_uint(fb[nf][1].y);
                    MMA_TF32(acc[mf][nf], al0, al1, al2, al3, bh0, bh1);   // a_lo * b_hi
                    MMA_TF32(acc[mf][nf], ah0, ah1, ah2, ah3, bl0, bl1);   // a_hi * b_lo
                    MMA_TF32(acc[mf][nf], ah0, ah1, ah2, ah3, bh0, bh1);   // a_hi * b_hi
                }
            }
        }
    }

    // ---- epilogue ----
#pragma unroll
    for (int mf = 0; mf < 2; mf++) {
#pragma unroll
        for (int nf = 0; nf < 4; nf++) {
            const int nc = n0 + warpN * 32 + nf * 8 + 2 * tg;
            const int r0 = m0 + warpM * 32 + mf * 16 + g;
            const int r1 = r0 + 8;
            float c0 = acc[mf][nf][0], c1 = acc[mf][nf][1];
            float c2 = acc[mf][nf][2], c3 = acc[mf][nf][3];
            if (MODE == 0) {
                const float b0 = aux[nc], b1 = aux[nc + 1];
                *(float2*)&out[(size_t)r0 * 768 + nc] = make_float2(c0 + b0, c1 + b1);
                *(float2*)&out[(size_t)r1 * 768 + nc] = make_float2(c2 + b0, c3 + b1);
            } else if (MODE == 2) {
                const float b0 = 0.25f * (aux[nc] + aux[768 + nc] + aux[1536 + nc] + aux[2304 + nc]);
                const float b1 = 0.25f * (aux[nc + 1] + aux[768 + nc + 1] + aux[1536 + nc + 1] + aux[2304 + nc + 1]);
                *(float2*)&out[(size_t)r0 * 768 + nc] = make_float2(0.25f * c0 + b0, 0.25f * c1 + b1);
                *(float2*)&out[(size_t)r1 * 768 + nc] = make_float2(0.25f * c2 + b0, 0.25f * c3 + b1);
            } else {
                // rope: head = blockIdx.x (N-tile == one head), pair index i
                const int h = blockIdx.x;
                const int i = warpN * 16 + nf * 4 + tg;
                {
                    const int t = r0 & 1023, bb = r0 >> 10;
                    float2 rc = g_ropetab[t * 32 + i];
                    float* qp = &out[(((size_t)(bb * H_TOT + h)) * T_LEN + t) * DH];
                    qp[i]      = c0 * rc.x - c1 * rc.y;
                    qp[i + 32] = c0 * rc.y + c1 * rc.x;
                }
                {
                    const int t = r1 & 1023, bb = r1 >> 10;
                    float2 rc = g_ropetab[t * 32 + i];
                    float* qp = &out[(((size_t)(bb * H_TOT + h)) * T_LEN + t) * DH];
                    qp[i]      = c2 * rc.x - c3 * rc.y;
                    qp[i + 32] = c2 * rc.y + c3 * rc.x;
                }
            }
        }
    }
}

// ================= K wedge + rope: kbase -> krope[b][h][t][d] ====================
__global__ __launch_bounds__(128) void kwr_kernel(const float* __restrict__ kbase,
                                                  const float* __restrict__ wedgeA,
                                                  const float* __restrict__ wbias,
                                                  float* __restrict__ krope) {
    extern __shared__ float kwr_sm[];
    float* Ms  = kwr_sm;            // 4096 floats
    float* kbs = kwr_sm + 4096;     // 128*65 floats
    const int h = blockIdx.y, hj = h % 12;
    const int m0 = blockIdx.x * 128;
    const int tid = threadIdx.x;

    for (int i = tid; i < 4096; i += 128) {
        int e = i >> 6, d = i & 63;
        float v = wedgeA[e * 64 + d] - wedgeA[d * 64 + e];
        if (e == d) v += 1.0f + wbias[h * 64 + d];
        Ms[i] = v;
    }
    for (int i = tid; i < 2048; i += 128) {
        int r = i >> 4, c4 = (i & 15) * 4;
        float4 v = *(const float4*)&kbase[(size_t)(m0 + r) * 768 + hj * 64 + c4];
        float* dst = &kbs[r * 65 + c4];
        dst[0] = v.x; dst[1] = v.y; dst[2] = v.z; dst[3] = v.w;
    }
    __syncthreads();

    const int m = m0 + tid, b = m >> 10, t = m & 1023;
    u64 acc2[32];
#pragma unroll
    for (int i = 0; i < 32; i++) acc2[i] = 0ull;
    const float* kr = &kbs[tid * 65];
    for (int e = 0; e < 64; ++e) {
        float kv = kr[e];
        u64 kv2 = f2pack(kv, kv);
        const u64* ms = (const u64*)&Ms[e * 64];
#pragma unroll
        for (int i = 0; i < 32; i++) acc2[i] = f2fma(kv2, ms[i], acc2[i]);
    }
    float* kp = &krope[(((size_t)(b * H_TOT + h)) * T_LEN + t) * DH];
    const float2* rt = &g_ropetab[t * 32];
#pragma unroll
    for (int i = 0; i < 32; i++) {
        float2 w = f2unpack(acc2[i]);
        float2 rc = rt[i];
        kp[i]      = w.x * rc.x - w.y * rc.y;
        kp[i + 32] = w.x * rc.y + w.y * rc.x;
    }
}

// ================= fused attention: scores + online softmax + top4 + MLP =========
__global__ __launch_bounds__(256) void attn_kernel(const float* __restrict__ qrope,
                                                   const float* __restrict__ krope,
                                                   const float* __restrict__ sink,
                                                   const float* __restrict__ vnull,
                                                   const float* __restrict__ V1w,
                                                   const float* __restrict__ V1b,
                                                   const float* __restrict__ V2w,
                                                   const float* __restrict__ V2b) {
    extern __shared__ float sm[];       // >= 33280 floats
    __shared__ float sV1b[256];

    const int bh = blockIdx.y;               // 0..95
    const int b = bh / H_TOT, h = bh % H_TOT;
    const int xt = (gridDim.x - 1) - blockIdx.x;   // heavy tiles first
    const int t = xt * 256 + threadIdx.x;

    // q row packed as f32x2
    u64 q2[32];
    {
        const ulonglong2* qp = (const ulonglong2*)&qrope[((size_t)bh * T_LEN + t) * DH];
#pragma unroll
        for (int i = 0; i < 16; i++) { ulonglong2 v = qp[i]; q2[2 * i] = v.x; q2[2 * i + 1] = v.y; }
    }

    float mrun = -CUDART_INF_F, lrun = 0.f;
    float ts0 = -CUDART_INF_F, ts1 = -CUDART_INF_F, ts2 = -CUDART_INF_F, ts3 = -CUDART_INF_F;
    int ti0 = 0, ti1 = 0, ti2 = 0, ti3 = 0;

    float* ks = sm;
    const int sEnd = xt * 256 + 255;

    for (int s0 = 0; s0 <= sEnd; s0 += 128) {
        __syncthreads();
        {
            const float4* kg = (const float4*)&krope[((size_t)bh * T_LEN + s0) * DH];
            float4* d4 = (float4*)ks;
            for (int i = threadIdx.x; i < 2048; i += 256) d4[i] = kg[i];
        }
        __syncthreads();

        const int sMax = min(t, s0 + 127);
        for (int s = s0; s <= sMax; ++s) {
            const ulonglong2* kr = (const ulonglong2*)(ks + (s - s0) * DH);
            u64 a0 = 0ull, a1 = 0ull, a2 = 0ull, a3 = 0ull;
#pragma unroll
            for (int i = 0; i < 16; i += 2) {
                ulonglong2 kva = kr[i];
                ulonglong2 kvb = kr[i + 1];
                a0 = f2fma(q2[2 * i],     kva.x, a0);
                a1 = f2fma(q2[2 * i + 1], kva.y, a1);
                a2 = f2fma(q2[2 * i + 2], kvb.x, a2);
                a3 = f2fma(q2[2 * i + 3], kvb.y, a3);
            }
            float sc = ((f2sum(a0) + f2sum(a1)) + (f2sum(a2) + f2sum(a3))) * 0.125f;

            if (sc <= mrun) {
                lrun += __expf(sc - mrun);
            } else {
                lrun = fmaf(lrun, __expf(mrun - sc), 1.0f);
                mrun = sc;
            }
            if (sc > ts3) {
                if (sc > ts2) {
                    ts3 = ts2; ti3 = ti2;
                    if (sc > ts1) {
                        ts2 = ts1; ti2 = ti1;
                        if (sc > ts0) {
                            ts1 = ts0; ti1 = ti0;
                            ts0 = sc; ti0 = s;
                        } else { ts1 = sc; ti1 = s; }
                    } else { ts2 = sc; ti2 = s; }
                } else { ts3 = sc; ti3 = s; }
            }
        }
    }

    // final normalization with sink
    const float sk = sink[h];
    const float mf = fmaxf(mrun, sk);
    const float Z = lrun * __expf(mrun - mf) + __expf(sk - mf);
    const float invZ = 1.0f / Z;
    const float psink = __expf(sk - mf) * invZ;
    float p0 = __expf(ts0 - mf) * invZ;
    float p1 = __expf(ts1 - mf) * invZ;
    float p2 = __expf(ts2 - mf) * invZ;
    float p3 = __expf(ts3 - mf) * invZ;
    const float winv = 1.0f / (p0 + p1 + p2 + p3 + 1e-9f);
    p0 *= winv; p1 *= winv; p2 *= winv; p3 *= winv;

    // marker gather (f32x2)
    u64 mk[32];
    {
        u64 w0 = f2pack(p0, p0), w1 = f2pack(p1, p1), w2 = f2pack(p2, p2), w3 = f2pack(p3, p3);
        const ulonglong2* kp0 = (const ulonglong2*)&krope[((size_t)bh * T_LEN + ti0) * DH];
        const ulonglong2* kp1 = (const ulonglong2*)&krope[((size_t)bh * T_LEN + ti1) * DH];
        const ulonglong2* kp2 = (const ulonglong2*)&krope[((size_t)bh * T_LEN + ti2) * DH];
        const ulonglong2* kp3 = (const ulonglong2*)&krope[((size_t)bh * T_LEN + ti3) * DH];
#pragma unroll
        for (int i = 0; i < 16; i++) {
            ulonglong2 va = kp0[i], vb = kp1[i], vc = kp2[i], vd = kp3[i];
            mk[2 * i]     = f2fma(w0, va.x, f2fma(w1, vb.x, f2fma(w2, vc.x, f2fma(w3, vd.x, 0ull))));
            mk[2 * i + 1] = f2fma(w0, va.y, f2fma(w1, vb.y, f2fma(w2, vc.y, f2fma(w3, vd.y, 0ull))));
        }
    }

    // stage V1 (row-major) and V2^T (pad 66) into smem
    __syncthreads();
    float* V1s = sm;                 // 16384 floats
    float* V2t = sm + 16384;         // 256*66 floats
    for (int i = threadIdx.x; i < 4096; i += 256) ((float4*)V1s)[i] = ((const float4*)V1w)[i];
    for (int i = threadIdx.x; i < 16384; i += 256) {
        int dd = i >> 8, j = i & 255;
        V2t[j * 66 + dd] = V2w[i];
    }
    if (threadIdx.x < 256) sV1b[threadIdx.x] = V1b[threadIdx.x];
    __syncthreads();

    u64 out2[32];
    {
        const u64* vb2 = (const u64*)V2b;
#pragma unroll
        for (int i = 0; i < 32; i++) out2[i] = vb2[i];
    }

    for (int j = 0; j < 256; ++j) {
        const ulonglong2* v1 = (const ulonglong2*)(V1s + j * 64);
        u64 z0 = 0ull, z1 = 0ull, z2 = 0ull, z3 = 0ull;
#pragma unroll
        for (int i = 0; i < 16; i += 2) {
            ulonglong2 va = v1[i];
            ulonglong2 vb = v1[i + 1];
            z0 = f2fma(mk[2 * i],     va.x, z0);
            z1 = f2fma(mk[2 * i + 1], va.y, z1);
            z2 = f2fma(mk[2 * i + 2], vb.x, z2);
            z3 = f2fma(mk[2 * i + 3], vb.y, z3);
        }
        float z = ((f2sum(z0) + f2sum(z1)) + (f2sum(z2) + f2sum(z3))) + sV1b[j];
        float g = 0.5f * z * (1.0f + erff(z * 0.70710678118f));
        u64 g2 = f2pack(g, g);
        const u64* v2 = (const u64*)(V2t + j * 66);
#pragma unroll
        for (int i = 0; i < 32; i++) out2[i] = f2fma(g2, v2[i], out2[i]);
    }

    // write context + sink contribution: ctx[b*1024+t][br*768 + hj*64 + d]
    const int br = h / 12, hj = h % 12;
    float* outp = &g_ctx[((size_t)(b * T_LEN + t)) * NQ + br * D_MODEL + hj * 64];
    const float* vn = vnull + h * 64;
#pragma unroll
    for (int i = 0; i < 32; i++) {
        float2 v = f2unpack(out2[i]);
        v.x = fmaf(psink, vn[2 * i], v.x);
        v.y = fmaf(psink, vn[2 * i + 1], v.y);
        ((float2*)outp)[i] = v;
    }
}

// ================= launcher =================
extern "C" void kernel_launch(void* const* d_in, const int* in_sizes, int n_in,
                              void* d_out, int out_size) {
    const float* A      = (const float*)d_in[0];
    const float* X      = (const float*)d_in[1];
    const float* WKw    = (const float*)d_in[2];
    const float* WKb    = (const float*)d_in[3];
    const float* WQw    = (const float*)d_in[4];
    const float* wedgeA = (const float*)d_in[5];
    const float* wbias  = (const float*)d_in[6];
    const float* sink   = (const float*)d_in[7];
    const float* vnull  = (const float*)d_in[8];
    const float* V1w    = (const float*)d_in[9];
    const float* V1b    = (const float*)d_in[10];
    const float* V2w    = (const float*)d_in[11];
    const float* V2b    = (const float*)d_in[12];
    const float* WOw    = (const float*)d_in[13];
    const float* WOb    = (const float*)d_in[14];
    float* Y = (float*)d_out;

    float *wq2, *wot, *kbase, *qrope, *krope, *ctx;
    cudaGetSymbolAddress((void**)&wq2,   g_wq2);
    cudaGetSymbolAddress((void**)&wot,   g_wot);
    cudaGetSymbolAddress((void**)&kbase, g_kbase);
    cudaGetSymbolAddress((void**)&qrope, g_qrope);
    cudaGetSymbolAddress((void**)&krope, g_krope);
    cudaGetSymbolAddress((void**)&ctx,   g_ctx);

    cudaFuncSetAttribute(attn_kernel, cudaFuncAttributeMaxDynamicSharedMemorySize, 133120);
    cudaFuncSetAttribute(kwr_kernel,  cudaFuncAttributeMaxDynamicSharedMemorySize, 50176);

    ropetab_kernel<<<128, 256>>>();
    foldwq_kernel<<<dim3(48, 12), 256>>>(WQw, wedgeA, wbias, wq2);
    transwo_kernel<<<dim3(24, 24, 4), 256>>>(WOw, wot);

    // K projection: kbase = X @ WK^T + b
    gemm_tf32_kernel<0><<<dim3(12, 16), 256>>>(X, WKw, 768, WKb, kbase);
    // Q projection (wedge folded) + rope epilogue
    gemm_tf32_kernel<1><<<dim3(48, 16), 256>>>(A, wq2, 768, nullptr, qrope);
    // K wedge + rope
    kwr_kernel<<<dim3(16, 48), 128, 50176>>>(kbase, wedgeA, wbias, krope);
    // attention + MLP + sink
    attn_kernel<<<dim3(4, 96), 256, 133120>>>(qrope, krope, sink, vnull,
                                              V1w, V1b, V2w, V2b);
    // output projection: Y = 0.25 * ctx @ WOt^T + mean bias
    gemm_tf32_kernel<2><<<dim3(12, 16), 256>>>(ctx, wot, 3072, WOb, Y);
}